// round 3
// baseline (speedup 1.0000x reference)
#include <cuda_runtime.h>

#define N_NODES 20000
#define N_EDGES 320000
#define D_IN    300
#define EMB     256

// ---------------- scratch (device globals; no allocation allowed) ----------
__device__ float g_tmp[N_NODES * EMB];   // GEMM output / message source
__device__ float g_hA [N_NODES * EMB];   // ping
__device__ float g_hB [N_NODES * EMB];   // pong
__device__ float g_dinv[N_NODES];
__device__ int   g_cnt [N_NODES];        // in-degree (excl. self-loop)
__device__ int   g_rowptr[N_NODES + 1];
__device__ int   g_fill[N_NODES];        // scatter cursor
__device__ int   g_srcs[N_EDGES];        // CSR column (src) indices by dst

// ---------------- CSR build -------------------------------------------------
__global__ void cnt_zero_kernel() {
    int i = blockIdx.x * blockDim.x + threadIdx.x;
    if (i < N_NODES) g_cnt[i] = 0;
}

__global__ void hist_kernel(const int* __restrict__ ei) {
    int e = blockIdx.x * blockDim.x + threadIdx.x;
    if (e < N_EDGES) atomicAdd(&g_cnt[ei[N_EDGES + e]], 1);
}

// single-block exclusive scan over g_cnt -> g_rowptr / g_fill, plus dinv
__global__ void __launch_bounds__(1024) scan_kernel() {
    __shared__ int sh[1024];
    __shared__ int carry;
    int tid = threadIdx.x;
    if (tid == 0) { carry = 0; g_rowptr[0] = 0; }
    __syncthreads();
    for (int base = 0; base < N_NODES; base += 1024) {
        int idx = base + tid;
        int v = (idx < N_NODES) ? g_cnt[idx] : 0;
        sh[tid] = v;
        __syncthreads();
        for (int off = 1; off < 1024; off <<= 1) {
            int t = (tid >= off) ? sh[tid - off] : 0;
            __syncthreads();
            sh[tid] += t;
            __syncthreads();
        }
        int incl = sh[tid];
        if (idx < N_NODES) {
            g_rowptr[idx + 1] = carry + incl;
            g_fill[idx]       = carry + incl - v;
            g_dinv[idx]       = rsqrtf((float)v + 1.0f);   // +1 self-loop
        }
        __syncthreads();
        if (tid == 1023) carry += sh[1023];
        __syncthreads();
    }
}

__global__ void scatter_kernel(const int* __restrict__ ei) {
    int e = blockIdx.x * blockDim.x + threadIdx.x;
    if (e < N_EDGES) {
        int s = ei[e];
        int d = ei[N_EDGES + e];
        int pos = atomicAdd(&g_fill[d], 1);
        g_srcs[pos] = s;
    }
}

// ---------------- fused aggregation (pull / gather, no float atomics) ------
// one warp per dst node:
// out[d] = bias + tmp[d]*dinv[d]^2 + sum_{s in N(d)} tmp[s]*dinv[s]*dinv[d]
__global__ void __launch_bounds__(256)
agg_kernel(const float* __restrict__ tmp, const float* __restrict__ bias,
           float* __restrict__ out) {
    int warp = (blockIdx.x * blockDim.x + threadIdx.x) >> 5;
    int lane = threadIdx.x & 31;
    if (warp >= N_NODES) return;

    float dd = g_dinv[warp];
    float ws = dd * dd;
    const float4* tp = reinterpret_cast<const float4*>(tmp);
    const float4* bp = reinterpret_cast<const float4*>(bias);
    long rb = (long)warp * 64;

    float4 b0 = bp[lane], b1 = bp[lane + 32];
    float4 t0 = tp[rb + lane], t1 = tp[rb + 32 + lane];
    float4 a0, a1;
    a0.x = fmaf(t0.x, ws, b0.x); a0.y = fmaf(t0.y, ws, b0.y);
    a0.z = fmaf(t0.z, ws, b0.z); a0.w = fmaf(t0.w, ws, b0.w);
    a1.x = fmaf(t1.x, ws, b1.x); a1.y = fmaf(t1.y, ws, b1.y);
    a1.z = fmaf(t1.z, ws, b1.z); a1.w = fmaf(t1.w, ws, b1.w);

    int beg = g_rowptr[warp], end = g_rowptr[warp + 1];
    for (int e = beg; e < end; e++) {
        int s = g_srcs[e];
        float w = g_dinv[s] * dd;
        long sb = (long)s * 64;
        float4 u0 = tp[sb + lane], u1 = tp[sb + 32 + lane];
        a0.x = fmaf(u0.x, w, a0.x); a0.y = fmaf(u0.y, w, a0.y);
        a0.z = fmaf(u0.z, w, a0.z); a0.w = fmaf(u0.w, w, a0.w);
        a1.x = fmaf(u1.x, w, a1.x); a1.y = fmaf(u1.y, w, a1.y);
        a1.z = fmaf(u1.z, w, a1.z); a1.w = fmaf(u1.w, w, a1.w);
    }
    reinterpret_cast<float4*>(out)[rb + lane]      = a0;
    reinterpret_cast<float4*>(out)[rb + 32 + lane] = a1;
}

// ---------------- SGEMM: C[M,256] = op(A[M,K]) @ B[K,256] (+bias)(+relu) ---
template<bool RELU_IN, bool HAS_BIAS, bool RELU_OUT>
__global__ void __launch_bounds__(256)
sgemm_kernel(const float* __restrict__ A, const float* __restrict__ B,
             const float* __restrict__ bias, float* __restrict__ C,
             int M, int K) {
    constexpr int BM = 128, BN = 128, BK = 16;
    constexpr int LDA = BM + 4;
    __shared__ float As[BK][LDA];
    __shared__ float Bs[BK][BN];

    int tid = threadIdx.x;
    int bm = blockIdx.x * BM;
    int bn = blockIdx.y * BN;
    int tx = tid & 15;
    int ty = tid >> 4;

    int a_k  = tid & 15;
    int a_m0 = tid >> 4;
    int b_c  = tid & 127;
    int b_k0 = (tid >> 7) * 8;

    float acc[8][8];
#pragma unroll
    for (int i = 0; i < 8; i++)
#pragma unroll
        for (int j = 0; j < 8; j++) acc[i][j] = 0.f;

    for (int k0 = 0; k0 < K; k0 += BK) {
#pragma unroll
        for (int i = 0; i < 8; i++) {
            int m  = a_m0 + i * 16;
            int gm = bm + m;
            int gk = k0 + a_k;
            float v = 0.f;
            if (gm < M && gk < K) v = A[(long)gm * K + gk];
            if (RELU_IN) v = fmaxf(v, 0.f);
            As[a_k][m] = v;
        }
#pragma unroll
        for (int i = 0; i < 8; i++) {
            int k  = b_k0 + i;
            int gk = k0 + k;
            float v = 0.f;
            if (gk < K) v = B[(long)gk * 256 + bn + b_c];
            Bs[k][b_c] = v;
        }
        __syncthreads();

#pragma unroll
        for (int kk = 0; kk < BK; kk++) {
            float ra[8], rbv[8];
#pragma unroll
            for (int i = 0; i < 8; i++) ra[i] = As[kk][ty * 8 + i];
#pragma unroll
            for (int j = 0; j < 8; j++) rbv[j] = Bs[kk][tx * 8 + j];
#pragma unroll
            for (int i = 0; i < 8; i++)
#pragma unroll
                for (int j = 0; j < 8; j++)
                    acc[i][j] = fmaf(ra[i], rbv[j], acc[i][j]);
        }
        __syncthreads();
    }

#pragma unroll
    for (int i = 0; i < 8; i++) {
        int gm = bm + ty * 8 + i;
        if (gm >= M) continue;
#pragma unroll
        for (int j = 0; j < 8; j++) {
            int gn = bn + tx * 8 + j;
            float v = acc[i][j];
            if (HAS_BIAS) v += bias[gn];
            if (RELU_OUT) v = fmaxf(v, 0.f);
            C[(long)gm * 256 + gn] = v;
        }
    }
}

// ---------------- launch ----------------------------------------------------
extern "C" void kernel_launch(void* const* d_in, const int* in_sizes, int n_in,
                              void* d_out, int out_size) {
    const float* x  = (const float*)d_in[0];
    const int*   ei = (const int*)d_in[1];          // int32 (JAX x64 disabled)
    const float* W0 = (const float*)d_in[2],  *b0 = (const float*)d_in[3];
    const float* W1 = (const float*)d_in[4],  *b1 = (const float*)d_in[5];
    const float* W2 = (const float*)d_in[6],  *b2 = (const float*)d_in[7];
    const float* M1 = (const float*)d_in[8],  *m1b = (const float*)d_in[9];
    const float* M2 = (const float*)d_in[10], *m2b = (const float*)d_in[11];
    const float* M3 = (const float*)d_in[12], *m3b = (const float*)d_in[13];
    float* out = (float*)d_out;

    float *tmp, *hA, *hB;
    cudaGetSymbolAddress((void**)&tmp, g_tmp);
    cudaGetSymbolAddress((void**)&hA,  g_hA);
    cudaGetSymbolAddress((void**)&hB,  g_hB);

    const int TPB = 256;
    int nb_nodes = (N_NODES + TPB - 1) / TPB;
    int nb_edges = (N_EDGES + TPB - 1) / TPB;

    // CSR build + normalization
    cnt_zero_kernel<<<nb_nodes, TPB>>>();
    hist_kernel   <<<nb_edges, TPB>>>(ei);
    scan_kernel   <<<1, 1024>>>();
    scatter_kernel<<<nb_edges, TPB>>>(ei);

    dim3 gg((N_NODES + 127) / 128, 2);
    int agg_blocks = (N_NODES * 32 + TPB - 1) / TPB;

    // conv0
    sgemm_kernel<false, false, false><<<gg, TPB>>>(x, W0, nullptr, tmp, N_NODES, D_IN);
    agg_kernel<<<agg_blocks, TPB>>>(tmp, b0, hA);
    // conv1 (relu on input fused into GEMM A-load)
    sgemm_kernel<true, false, false><<<gg, TPB>>>(hA, W1, nullptr, tmp, N_NODES, EMB);
    agg_kernel<<<agg_blocks, TPB>>>(tmp, b1, hB);
    // conv2 (no relu after aggregation)
    sgemm_kernel<true, false, false><<<gg, TPB>>>(hB, W2, nullptr, tmp, N_NODES, EMB);
    agg_kernel<<<agg_blocks, TPB>>>(tmp, b2, hA);

    // MLP
    sgemm_kernel<false, true, true ><<<gg, TPB>>>(hA, M1, m1b, hB, N_NODES, EMB);
    sgemm_kernel<false, true, true ><<<gg, TPB>>>(hB, M2, m2b, hA, N_NODES, EMB);
    sgemm_kernel<false, true, false><<<gg, TPB>>>(hA, M3, m3b, out, N_NODES, EMB);
}

// round 8
// speedup vs baseline: 1.7426x; 1.7426x over previous
#include <cuda_runtime.h>
#include <cuda_bf16.h>
#include <cstdint>

#define N_NODES 20000
#define N_EDGES 320000
#define D_IN    300
#define EMB     256

// ---------------- scratch (device globals; no allocation allowed) ----------
__device__ float g_tmp[N_NODES * EMB];
__device__ float g_hA [N_NODES * EMB];
__device__ float g_hB [N_NODES * EMB];
__device__ float g_dinv[N_NODES];
__device__ int   g_cnt [N_NODES];
__device__ int   g_rowptr[N_NODES + 1];
__device__ int   g_fill[N_NODES];
__device__ int   g_srcs[N_EDGES];
// split-bf16 operands (max K' = 3*320 = 960)
__device__ __align__(16) __nv_bfloat16 g_a2[N_NODES * 960];
__device__ __align__(16) __nv_bfloat16 g_b2[256 * 960];

// ---------------- PTX helpers (baseline compute_103-safe only) --------------
__device__ __forceinline__ uint32_t smem_u32(const void* p) {
    uint32_t a;
    asm("{ .reg .u64 t; cvta.to.shared.u64 t, %1; cvt.u32.u64 %0, t; }"
        : "=r"(a) : "l"(p));
    return a;
}
#define CP_ASYNC16Z(dst, src, sz) \
    asm volatile("cp.async.cg.shared.global [%0], [%1], 16, %2;" \
                 :: "r"(dst), "l"(src), "r"(sz) : "memory")
#define CP_ASYNC16(dst, src) \
    asm volatile("cp.async.cg.shared.global [%0], [%1], 16;" \
                 :: "r"(dst), "l"(src) : "memory")
#define CP_COMMIT() asm volatile("cp.async.commit_group;" ::: "memory")
#define CP_WAIT1()  asm volatile("cp.async.wait_group 1;" ::: "memory")
#define CP_WAIT0()  asm volatile("cp.async.wait_group 0;" ::: "memory")
#define LDM_X4(r0, r1, r2, r3, a) \
    asm volatile("ldmatrix.sync.aligned.m8n8.x4.shared.b16 {%0,%1,%2,%3}, [%4];" \
                 : "=r"(r0), "=r"(r1), "=r"(r2), "=r"(r3) : "r"(a))
#define MMA16816(d, a, b0v, b1v) \
    asm volatile("mma.sync.aligned.m16n8k16.row.col.f32.bf16.bf16.f32 " \
                 "{%0,%1,%2,%3},{%4,%5,%6,%7},{%8,%9},{%0,%1,%2,%3};" \
                 : "+f"((d)[0]), "+f"((d)[1]), "+f"((d)[2]), "+f"((d)[3]) \
                 : "r"((a)[0]), "r"((a)[1]), "r"((a)[2]), "r"((a)[3]), \
                   "r"(b0v), "r"(b1v))

// ---------------- CSR build -------------------------------------------------
__global__ void cnt_zero_kernel() {
    int i = blockIdx.x * blockDim.x + threadIdx.x;
    if (i < N_NODES) g_cnt[i] = 0;
}
__global__ void hist_kernel(const int* __restrict__ ei) {
    int e = blockIdx.x * blockDim.x + threadIdx.x;
    if (e < N_EDGES) atomicAdd(&g_cnt[ei[N_EDGES + e]], 1);
}
__global__ void __launch_bounds__(1024) scan_kernel() {
    __shared__ int sh[1024];
    __shared__ int carry;
    int tid = threadIdx.x;
    if (tid == 0) { carry = 0; g_rowptr[0] = 0; }
    __syncthreads();
    for (int base = 0; base < N_NODES; base += 1024) {
        int idx = base + tid;
        int v = (idx < N_NODES) ? g_cnt[idx] : 0;
        sh[tid] = v;
        __syncthreads();
        for (int off = 1; off < 1024; off <<= 1) {
            int t = (tid >= off) ? sh[tid - off] : 0;
            __syncthreads();
            sh[tid] += t;
            __syncthreads();
        }
        int incl = sh[tid];
        if (idx < N_NODES) {
            g_rowptr[idx + 1] = carry + incl;
            g_fill[idx]       = carry + incl - v;
            g_dinv[idx]       = rsqrtf((float)v + 1.0f);
        }
        __syncthreads();
        if (tid == 1023) carry += sh[1023];
        __syncthreads();
    }
}
__global__ void scatter_kernel(const int* __restrict__ ei) {
    int e = blockIdx.x * blockDim.x + threadIdx.x;
    if (e < N_EDGES) {
        int s = ei[e];
        int d = ei[N_EDGES + e];
        int pos = atomicAdd(&g_fill[d], 1);
        g_srcs[pos] = s;
    }
}

// ---------------- aggregation (pull, no float atomics) ----------------------
__global__ void __launch_bounds__(256)
agg_kernel(const float* __restrict__ tmp, const float* __restrict__ bias,
           float* __restrict__ out) {
    int warp = (blockIdx.x * blockDim.x + threadIdx.x) >> 5;
    int lane = threadIdx.x & 31;
    if (warp >= N_NODES) return;
    float dd = g_dinv[warp];
    float ws = dd * dd;
    const float4* tp = reinterpret_cast<const float4*>(tmp);
    const float4* bp = reinterpret_cast<const float4*>(bias);
    long rb = (long)warp * 64;
    float4 b0 = bp[lane], b1 = bp[lane + 32];
    float4 t0 = tp[rb + lane], t1 = tp[rb + 32 + lane];
    float4 a0, a1;
    a0.x = fmaf(t0.x, ws, b0.x); a0.y = fmaf(t0.y, ws, b0.y);
    a0.z = fmaf(t0.z, ws, b0.z); a0.w = fmaf(t0.w, ws, b0.w);
    a1.x = fmaf(t1.x, ws, b1.x); a1.y = fmaf(t1.y, ws, b1.y);
    a1.z = fmaf(t1.z, ws, b1.z); a1.w = fmaf(t1.w, ws, b1.w);
    int beg = g_rowptr[warp], end = g_rowptr[warp + 1];
    for (int e = beg; e < end; e++) {
        int s = g_srcs[e];
        float w = g_dinv[s] * dd;
        long sb = (long)s * 64;
        float4 u0 = tp[sb + lane], u1 = tp[sb + 32 + lane];
        a0.x = fmaf(u0.x, w, a0.x); a0.y = fmaf(u0.y, w, a0.y);
        a0.z = fmaf(u0.z, w, a0.z); a0.w = fmaf(u0.w, w, a0.w);
        a1.x = fmaf(u1.x, w, a1.x); a1.y = fmaf(u1.y, w, a1.y);
        a1.z = fmaf(u1.z, w, a1.z); a1.w = fmaf(u1.w, w, a1.w);
    }
    reinterpret_cast<float4*>(out)[rb + lane]      = a0;
    reinterpret_cast<float4*>(out)[rb + 32 + lane] = a1;
}

// ---------------- split-bf16 conversions ------------------------------------
__device__ __forceinline__ void split_bf16(float x, __nv_bfloat16& hi,
                                           __nv_bfloat16& lo) {
    hi = __float2bfloat16_rn(x);
    lo = __float2bfloat16_rn(x - __bfloat162float(hi));
}

// A2[m] = [hi(0..Kp) | lo | hi], zero-padded k in [K,Kp)
__global__ void a2_kernel(const float* __restrict__ src, int M, int K, int Kp,
                          int K3, int do_relu) {
    int idx = blockIdx.x * blockDim.x + threadIdx.x;
    if (idx >= M * Kp) return;
    int m = idx / Kp, k = idx - m * Kp;
    __nv_bfloat16 hi = __float2bfloat16_rn(0.f), lo = hi;
    if (k < K) {
        float x = src[(size_t)m * K + k];
        if (do_relu) x = fmaxf(x, 0.f);
        split_bf16(x, hi, lo);
    }
    size_t rb = (size_t)m * K3;
    g_a2[rb + k]          = hi;
    g_a2[rb + Kp + k]     = lo;
    g_a2[rb + 2 * Kp + k] = hi;
}

// B2t[n] = [hi | hi | lo] from W[K,256] (transposed), zero-padded
__global__ void b2_kernel(const float* __restrict__ W, int K, int Kp, int K3) {
    int idx = blockIdx.x * blockDim.x + threadIdx.x;
    if (idx >= 256 * Kp) return;
    int n = idx / Kp, k = idx - n * Kp;
    __nv_bfloat16 hi = __float2bfloat16_rn(0.f), lo = hi;
    if (k < K) split_bf16(W[(size_t)k * 256 + n], hi, lo);
    size_t rb = (size_t)n * K3;
    g_b2[rb + k]          = hi;
    g_b2[rb + Kp + k]     = hi;
    g_b2[rb + 2 * Kp + k] = lo;
}

// ---------------- bf16 HMMA GEMM: C[M,256] = A2[M,K3] @ B2t[256,K3]^T -------
// CTA 128x128, BK=32, 8 warps (4M x 2N), warp tile 32x64 (2x8 m16n8k16).
// SMEM rows padded to 80B (5 x 16B units) -> conflict-free ldmatrix.
#define ROWB 80
#define TILEB (128 * ROWB)        // 10240 bytes per operand tile

template<bool HAS_BIAS, bool RELU_OUT>
__global__ void __launch_bounds__(256)
hgemm_kernel(const __nv_bfloat16* __restrict__ A2,
             const __nv_bfloat16* __restrict__ B2,
             const float* __restrict__ bias,
             float* __restrict__ C, int M, int K3, int NK) {
    __shared__ __align__(128) char sm[2][2 * TILEB];

    int tid  = threadIdx.x;
    int wid  = tid >> 5;
    int lane = tid & 31;
    int bm = blockIdx.x * 128;
    int bn = blockIdx.y * 128;
    int wm = wid & 3;          // 0..3 : 32 M-rows each
    int wn = wid >> 2;         // 0..1 : 64 N-cols each

    uint32_t sbase = smem_u32(&sm[0][0]);

    // async loader: A tile 128x32 bf16 + B tile 128x32 bf16 into buffer `buf`
    auto issue = [&](int c, int buf) {
        int kb = c * 32;
        uint32_t aB = sbase + buf * (2 * TILEB);
        uint32_t bB = aB + TILEB;
#pragma unroll
        for (int i = 0; i < 2; i++) {
            int u = tid + i * 256;          // 0..511
            int r = u >> 2, un = u & 3;
            uint32_t dst = aB + r * ROWB + un * 16;
            const __nv_bfloat16* src = A2 + (size_t)(bm + r) * K3 + kb + un * 8;
            int sz = (bm + r < M) ? 16 : 0;
            CP_ASYNC16Z(dst, src, sz);
        }
#pragma unroll
        for (int i = 0; i < 2; i++) {
            int u = tid + i * 256;
            int r = u >> 2, un = u & 3;
            uint32_t dst = bB + r * ROWB + un * 16;
            const __nv_bfloat16* src = B2 + (size_t)(bn + r) * K3 + kb + un * 8;
            CP_ASYNC16(dst, src);
        }
        CP_COMMIT();
    };

    float acc[2][8][4];
#pragma unroll
    for (int mt = 0; mt < 2; mt++)
#pragma unroll
        for (int nt = 0; nt < 8; nt++)
#pragma unroll
            for (int q = 0; q < 4; q++) acc[mt][nt][q] = 0.f;

    issue(0, 0);
    for (int c = 0; c < NK; c++) {
        if (c + 1 < NK) { issue(c + 1, (c + 1) & 1); CP_WAIT1(); }
        else            { CP_WAIT0(); }
        __syncthreads();

        uint32_t aB = sbase + (c & 1) * (2 * TILEB);
        uint32_t bB = aB + TILEB;

        // B fragments: 8 ntiles, ldmatrix.x4 covers all 32 k (4 units)
        uint32_t breg[8][4];
#pragma unroll
        for (int nt = 0; nt < 8; nt++) {
            uint32_t addr = bB + (uint32_t)((wn * 64 + nt * 8 + (lane & 7)) * ROWB
                                            + (lane >> 3) * 16);
            LDM_X4(breg[nt][0], breg[nt][1], breg[nt][2], breg[nt][3], addr);
        }
#pragma unroll
        for (int kt = 0; kt < 2; kt++) {
            uint32_t areg[2][4];
#pragma unroll
            for (int mt = 0; mt < 2; mt++) {
                uint32_t addr = aB + (uint32_t)((wm * 32 + mt * 16 + (lane & 15)) * ROWB
                                                + (kt * 2 + (lane >> 4)) * 16);
                LDM_X4(areg[mt][0], areg[mt][1], areg[mt][2], areg[mt][3], addr);
            }
#pragma unroll
            for (int mt = 0; mt < 2; mt++)
#pragma unroll
                for (int nt = 0; nt < 8; nt++)
                    MMA16816(acc[mt][nt], areg[mt],
                             breg[nt][kt * 2], breg[nt][kt * 2 + 1]);
        }
        __syncthreads();
    }

    // epilogue: direct f32x2 stores from fragments
    int gid = lane >> 2, tig = lane & 3;
#pragma unroll
    for (int mt = 0; mt < 2; mt++) {
        int row0 = bm + wm * 32 + mt * 16 + gid;
#pragma unroll
        for (int nt = 0; nt < 8; nt++) {
            int col = bn + wn * 64 + nt * 8 + 2 * tig;
            float2 v0 = make_float2(acc[mt][nt][0], acc[mt][nt][1]);
            float2 v1 = make_float2(acc[mt][nt][2], acc[mt][nt][3]);
            if (HAS_BIAS) {
                float bx = bias[col], by = bias[col + 1];
                v0.x += bx; v0.y += by; v1.x += bx; v1.y += by;
            }
            if (RELU_OUT) {
                v0.x = fmaxf(v0.x, 0.f); v0.y = fmaxf(v0.y, 0.f);
                v1.x = fmaxf(v1.x, 0.f); v1.y = fmaxf(v1.y, 0.f);
            }
            if (row0 < M)
                *reinterpret_cast<float2*>(C + (size_t)row0 * 256 + col) = v0;
            if (row0 + 8 < M)
                *reinterpret_cast<float2*>(C + (size_t)(row0 + 8) * 256 + col) = v1;
        }
    }
}

// ---------------- launch ----------------------------------------------------
extern "C" void kernel_launch(void* const* d_in, const int* in_sizes, int n_in,
                              void* d_out, int out_size) {
    const float* x  = (const float*)d_in[0];
    const int*   ei = (const int*)d_in[1];
    const float* W0 = (const float*)d_in[2],  *b0 = (const float*)d_in[3];
    const float* W1 = (const float*)d_in[4],  *b1 = (const float*)d_in[5];
    const float* W2 = (const float*)d_in[6],  *b2 = (const float*)d_in[7];
    const float* M1 = (const float*)d_in[8],  *m1b = (const float*)d_in[9];
    const float* M2 = (const float*)d_in[10], *m2b = (const float*)d_in[11];
    const float* M3 = (const float*)d_in[12], *m3b = (const float*)d_in[13];
    float* out = (float*)d_out;

    float *tmp, *hA, *hB;
    __nv_bfloat16 *a2p, *b2p;
    cudaGetSymbolAddress((void**)&tmp, g_tmp);
    cudaGetSymbolAddress((void**)&hA,  g_hA);
    cudaGetSymbolAddress((void**)&hB,  g_hB);
    cudaGetSymbolAddress((void**)&a2p, g_a2);
    cudaGetSymbolAddress((void**)&b2p, g_b2);

    const int TPB = 256;
    int nb_nodes = (N_NODES + TPB - 1) / TPB;
    int nb_edges = (N_EDGES + TPB - 1) / TPB;

    cnt_zero_kernel<<<nb_nodes, TPB>>>();
    hist_kernel   <<<nb_edges, TPB>>>(ei);
    scan_kernel   <<<1, 1024>>>();
    scatter_kernel<<<nb_edges, TPB>>>(ei);

    dim3 gg((N_NODES + 127) / 128, 2);      // 157 x 2
    int agg_blocks = (N_NODES * 32 + TPB - 1) / TPB;

    // conv0: K=300 -> Kp=320, K3=960, NK=30; others: 256 / 768 / 24
    const int Kp0 = 320, K30 = 960, NK0 = 30;
    const int Kp1 = 256, K31 = 768, NK1 = 24;
    int a2b0 = (N_NODES * Kp0 + TPB - 1) / TPB;
    int a2b1 = (N_NODES * Kp1 + TPB - 1) / TPB;
    int b2b0 = (256 * Kp0 + TPB - 1) / TPB;
    int b2b1 = (256 * Kp1 + TPB - 1) / TPB;

    // conv0
    b2_kernel<<<b2b0, TPB>>>(W0, D_IN, Kp0, K30);
    a2_kernel<<<a2b0, TPB>>>(x, N_NODES, D_IN, Kp0, K30, 0);
    hgemm_kernel<false, false><<<gg, TPB>>>(a2p, b2p, nullptr, tmp, N_NODES, K30, NK0);
    agg_kernel<<<agg_blocks, TPB>>>(tmp, b0, hA);
    // conv1 (relu fused into A conversion)
    b2_kernel<<<b2b1, TPB>>>(W1, EMB, Kp1, K31);
    a2_kernel<<<a2b1, TPB>>>(hA, N_NODES, EMB, Kp1, K31, 1);
    hgemm_kernel<false, false><<<gg, TPB>>>(a2p, b2p, nullptr, tmp, N_NODES, K31, NK1);
    agg_kernel<<<agg_blocks, TPB>>>(tmp, b1, hB);
    // conv2
    b2_kernel<<<b2b1, TPB>>>(W2, EMB, Kp1, K31);
    a2_kernel<<<a2b1, TPB>>>(hB, N_NODES, EMB, Kp1, K31, 1);
    hgemm_kernel<false, false><<<gg, TPB>>>(a2p, b2p, nullptr, tmp, N_NODES, K31, NK1);
    agg_kernel<<<agg_blocks, TPB>>>(tmp, b2, hA);
    // MLP
    b2_kernel<<<b2b1, TPB>>>(M1, EMB, Kp1, K31);
    a2_kernel<<<a2b1, TPB>>>(hA, N_NODES, EMB, Kp1, K31, 0);
    hgemm_kernel<true, true><<<gg, TPB>>>(a2p, b2p, m1b, hB, N_NODES, K31, NK1);
    b2_kernel<<<b2b1, TPB>>>(M2, EMB, Kp1, K31);
    a2_kernel<<<a2b1, TPB>>>(hB, N_NODES, EMB, Kp1, K31, 0);
    hgemm_kernel<true, true><<<gg, TPB>>>(a2p, b2p, m2b, hA, N_NODES, K31, NK1);
    b2_kernel<<<b2b1, TPB>>>(M3, EMB, Kp1, K31);
    a2_kernel<<<a2b1, TPB>>>(hA, N_NODES, EMB, Kp1, K31, 0);
    hgemm_kernel<true, false><<<gg, TPB>>>(a2p, b2p, m3b, out, N_NODES, K31, NK1);
}

// round 9
// speedup vs baseline: 2.0289x; 1.1642x over previous
#include <cuda_runtime.h>
#include <cuda_bf16.h>
#include <cstdint>

#define N_NODES 20000
#define N_EDGES 320000
#define D_IN    300
#define EMB     256

// ---------------- scratch (device globals; no allocation allowed) ----------
__device__ float g_tmp[N_NODES * EMB];            // conv GEMM fp32 output
__device__ float g_dinv[N_NODES];
__device__ int   g_cnt [N_NODES];
__device__ int   g_rowptr[N_NODES + 1];
__device__ int   g_fill[N_NODES];
__device__ int   g_srcs[N_EDGES];
// split-bf16 activation buffers, layout per row: [hi(Kp) | lo(Kp)], stride 2*Kp
// capacity: conv0 needs Kp=320 -> stride 640
__device__ __align__(16) __nv_bfloat16 g_bufA[N_NODES * 640];
__device__ __align__(16) __nv_bfloat16 g_bufB[N_NODES * 640];
// all 6 weights, slot stride 256*640 ([hi|lo] per row)
__device__ __align__(16) __nv_bfloat16 g_w2[6 * 256 * 640];

// ---------------- PTX helpers ----------------------------------------------
__device__ __forceinline__ uint32_t smem_u32(const void* p) {
    uint32_t a;
    asm("{ .reg .u64 t; cvta.to.shared.u64 t, %1; cvt.u32.u64 %0, t; }"
        : "=r"(a) : "l"(p));
    return a;
}
#define CP_ASYNC16Z(dst, src, sz) \
    asm volatile("cp.async.cg.shared.global [%0], [%1], 16, %2;" \
                 :: "r"(dst), "l"(src), "r"(sz) : "memory")
#define CP_ASYNC16(dst, src) \
    asm volatile("cp.async.cg.shared.global [%0], [%1], 16;" \
                 :: "r"(dst), "l"(src) : "memory")
#define CP_COMMIT() asm volatile("cp.async.commit_group;" ::: "memory")
#define CP_WAIT1()  asm volatile("cp.async.wait_group 1;" ::: "memory")
#define CP_WAIT0()  asm volatile("cp.async.wait_group 0;" ::: "memory")
#define LDM_X4(r0, r1, r2, r3, a) \
    asm volatile("ldmatrix.sync.aligned.m8n8.x4.shared.b16 {%0,%1,%2,%3}, [%4];" \
                 : "=r"(r0), "=r"(r1), "=r"(r2), "=r"(r3) : "r"(a))
#define MMA16816(d, a, b0v, b1v) \
    asm volatile("mma.sync.aligned.m16n8k16.row.col.f32.bf16.bf16.f32 " \
                 "{%0,%1,%2,%3},{%4,%5,%6,%7},{%8,%9},{%0,%1,%2,%3};" \
                 : "+f"((d)[0]), "+f"((d)[1]), "+f"((d)[2]), "+f"((d)[3]) \
                 : "r"((a)[0]), "r"((a)[1]), "r"((a)[2]), "r"((a)[3]), \
                   "r"(b0v), "r"(b1v))

__device__ __forceinline__ void split_bf16(float x, __nv_bfloat16& hi,
                                           __nv_bfloat16& lo) {
    hi = __float2bfloat16_rn(x);
    lo = __float2bfloat16_rn(x - __bfloat162float(hi));
}
union Pack4 { __nv_bfloat16 h[4]; uint2 u; };
union Pack2 { __nv_bfloat16 h[2]; uint32_t u; };

// ---------------- CSR build -------------------------------------------------
__global__ void cnt_zero_kernel() {
    int i = blockIdx.x * blockDim.x + threadIdx.x;
    if (i < N_NODES) g_cnt[i] = 0;
}
__global__ void hist_kernel(const int* __restrict__ ei) {
    int e = blockIdx.x * blockDim.x + threadIdx.x;
    if (e < N_EDGES) atomicAdd(&g_cnt[ei[N_EDGES + e]], 1);
}
__global__ void __launch_bounds__(1024) scan_kernel() {
    __shared__ int sh[1024];
    __shared__ int carry;
    int tid = threadIdx.x;
    if (tid == 0) { carry = 0; g_rowptr[0] = 0; }
    __syncthreads();
    for (int base = 0; base < N_NODES; base += 1024) {
        int idx = base + tid;
        int v = (idx < N_NODES) ? g_cnt[idx] : 0;
        sh[tid] = v;
        __syncthreads();
        for (int off = 1; off < 1024; off <<= 1) {
            int t = (tid >= off) ? sh[tid - off] : 0;
            __syncthreads();
            sh[tid] += t;
            __syncthreads();
        }
        int incl = sh[tid];
        if (idx < N_NODES) {
            g_rowptr[idx + 1] = carry + incl;
            g_fill[idx]       = carry + incl - v;
            g_dinv[idx]       = rsqrtf((float)v + 1.0f);
        }
        __syncthreads();
        if (tid == 1023) carry += sh[1023];
        __syncthreads();
    }
}
__global__ void scatter_kernel(const int* __restrict__ ei) {
    int e = blockIdx.x * blockDim.x + threadIdx.x;
    if (e < N_EDGES) {
        int s = ei[e];
        int d = ei[N_EDGES + e];
        int pos = atomicAdd(&g_fill[d], 1);
        g_srcs[pos] = s;
    }
}

// ---------------- aggregation (pull) + fused relu + split-bf16 output ------
template<int RELU>
__global__ void __launch_bounds__(256)
agg_kernel(const float* __restrict__ tmp, const float* __restrict__ bias,
           __nv_bfloat16* __restrict__ outS) {
    int warp = (blockIdx.x * blockDim.x + threadIdx.x) >> 5;
    int lane = threadIdx.x & 31;
    if (warp >= N_NODES) return;
    float dd = g_dinv[warp];
    float ws = dd * dd;
    const float4* tp = reinterpret_cast<const float4*>(tmp);
    const float4* bp = reinterpret_cast<const float4*>(bias);
    long rb = (long)warp * 64;
    float4 b0 = bp[lane], b1 = bp[lane + 32];
    float4 t0 = tp[rb + lane], t1 = tp[rb + 32 + lane];
    float4 a0, a1;
    a0.x = fmaf(t0.x, ws, b0.x); a0.y = fmaf(t0.y, ws, b0.y);
    a0.z = fmaf(t0.z, ws, b0.z); a0.w = fmaf(t0.w, ws, b0.w);
    a1.x = fmaf(t1.x, ws, b1.x); a1.y = fmaf(t1.y, ws, b1.y);
    a1.z = fmaf(t1.z, ws, b1.z); a1.w = fmaf(t1.w, ws, b1.w);
    int e = g_rowptr[warp], end = g_rowptr[warp + 1];
    for (; e + 1 < end; e += 2) {
        int s0 = g_srcs[e], s1 = g_srcs[e + 1];
        float w0 = g_dinv[s0] * dd, w1 = g_dinv[s1] * dd;
        long sb0 = (long)s0 * 64, sb1 = (long)s1 * 64;
        float4 u0 = tp[sb0 + lane], u1 = tp[sb0 + 32 + lane];
        float4 v0 = tp[sb1 + lane], v1 = tp[sb1 + 32 + lane];
        a0.x = fmaf(u0.x, w0, a0.x); a0.y = fmaf(u0.y, w0, a0.y);
        a0.z = fmaf(u0.z, w0, a0.z); a0.w = fmaf(u0.w, w0, a0.w);
        a1.x = fmaf(u1.x, w0, a1.x); a1.y = fmaf(u1.y, w0, a1.y);
        a1.z = fmaf(u1.z, w0, a1.z); a1.w = fmaf(u1.w, w0, a1.w);
        a0.x = fmaf(v0.x, w1, a0.x); a0.y = fmaf(v0.y, w1, a0.y);
        a0.z = fmaf(v0.z, w1, a0.z); a0.w = fmaf(v0.w, w1, a0.w);
        a1.x = fmaf(v1.x, w1, a1.x); a1.y = fmaf(v1.y, w1, a1.y);
        a1.z = fmaf(v1.z, w1, a1.z); a1.w = fmaf(v1.w, w1, a1.w);
    }
    if (e < end) {
        int s0 = g_srcs[e];
        float w0 = g_dinv[s0] * dd;
        long sb0 = (long)s0 * 64;
        float4 u0 = tp[sb0 + lane], u1 = tp[sb0 + 32 + lane];
        a0.x = fmaf(u0.x, w0, a0.x); a0.y = fmaf(u0.y, w0, a0.y);
        a0.z = fmaf(u0.z, w0, a0.z); a0.w = fmaf(u0.w, w0, a0.w);
        a1.x = fmaf(u1.x, w0, a1.x); a1.y = fmaf(u1.y, w0, a1.y);
        a1.z = fmaf(u1.z, w0, a1.z); a1.w = fmaf(u1.w, w0, a1.w);
    }
    if (RELU) {
        a0.x = fmaxf(a0.x, 0.f); a0.y = fmaxf(a0.y, 0.f);
        a0.z = fmaxf(a0.z, 0.f); a0.w = fmaxf(a0.w, 0.f);
        a1.x = fmaxf(a1.x, 0.f); a1.y = fmaxf(a1.y, 0.f);
        a1.z = fmaxf(a1.z, 0.f); a1.w = fmaxf(a1.w, 0.f);
    }
    // split write: row stride 512 ([hi(256) | lo(256)])
    __nv_bfloat16* rp = outS + (size_t)warp * 512;
    float vs[2][4] = {{a0.x, a0.y, a0.z, a0.w}, {a1.x, a1.y, a1.z, a1.w}};
    int cols[2] = {4 * lane, 128 + 4 * lane};
#pragma unroll
    for (int h = 0; h < 2; h++) {
        Pack4 hi4, lo4;
#pragma unroll
        for (int q = 0; q < 4; q++) split_bf16(vs[h][q], hi4.h[q], lo4.h[q]);
        *reinterpret_cast<uint2*>(rp + cols[h])       = hi4.u;
        *reinterpret_cast<uint2*>(rp + 256 + cols[h]) = lo4.u;
    }
}

// ---------------- x -> split-bf16 (only remaining A conversion) -------------
__global__ void a2x_kernel(const float* __restrict__ src,
                           __nv_bfloat16* __restrict__ dst) {
    const int Kp = 320;
    int idx = blockIdx.x * blockDim.x + threadIdx.x;
    if (idx >= N_NODES * Kp) return;
    int m = idx / Kp, k = idx - m * Kp;
    __nv_bfloat16 hi = __float2bfloat16_rn(0.f), lo = hi;
    if (k < D_IN) split_bf16(src[(size_t)m * D_IN + k], hi, lo);
    size_t rb = (size_t)m * 640;
    dst[rb + k]      = hi;
    dst[rb + Kp + k] = lo;
}

// ---------------- all 6 weights -> split-bf16 in one kernel -----------------
// slot s at g_w2 + s*163840; W[K,256] transposed to [n][hi(Kp)|lo(Kp)]
__global__ void wconv_kernel(const float* __restrict__ W0,
                             const float* __restrict__ W1,
                             const float* __restrict__ W2,
                             const float* __restrict__ M1,
                             const float* __restrict__ M2,
                             const float* __restrict__ M3) {
    int idx = blockIdx.x * blockDim.x + threadIdx.x;
    const float* srcs[6] = {W0, W1, W2, M1, M2, M3};
    int slot, n, k, K, Kp;
    if (idx < 256 * 320) {
        slot = 0; n = idx / 320; k = idx - n * 320; K = D_IN; Kp = 320;
    } else {
        int r = idx - 256 * 320;
        if (r >= 5 * 256 * 256) return;
        slot = 1 + r / 65536; int q = r & 65535;
        n = q >> 8; k = q & 255; K = 256; Kp = 256;
    }
    __nv_bfloat16 hi = __float2bfloat16_rn(0.f), lo = hi;
    if (k < K) split_bf16(srcs[slot][(size_t)k * 256 + n], hi, lo);
    __nv_bfloat16* dst = g_w2 + (size_t)slot * 163840 + (size_t)n * 2 * Kp;
    dst[k]      = hi;
    dst[Kp + k] = lo;
}

// ---------------- bf16 HMMA GEMM --------------------------------------------
// logical C[M,256] = A[M,K] @ B[K,256], via 3*Kp/32 chunks over [hi|lo] data:
// A segs: hi,lo,hi ; B segs: hi,hi,lo  (drops only lo*lo term)
// CTA 128x128, BK=32, 8 warps (4M x 2N). SMEM rows padded to 80B.
#define ROWB 80
#define TILEB (128 * ROWB)

template<bool HAS_BIAS, bool RELU_OUT, bool WRITE_SPLIT>
__global__ void __launch_bounds__(256)
hgemm_kernel(const __nv_bfloat16* __restrict__ A2,
             const __nv_bfloat16* __restrict__ B2,
             const float* __restrict__ bias,
             float* __restrict__ C, __nv_bfloat16* __restrict__ Cs,
             int M, int Kp) {
    __shared__ __align__(128) char sm[2][2 * TILEB];

    int tid  = threadIdx.x;
    int wid  = tid >> 5;
    int lane = tid & 31;
    int bm = blockIdx.x * 128;
    int bn = blockIdx.y * 128;
    int wm = wid & 3;
    int wn = wid >> 2;
    int nseg = Kp >> 5;
    int NK = 3 * nseg;
    int KS = 2 * Kp;

    uint32_t sbase = smem_u32(&sm[0][0]);

    auto issue = [&](int c, int buf) {
        int seg = c / nseg, kc = c - seg * nseg;
        int ka = ((seg == 1) ? Kp : 0) + kc * 32;
        int kb = ((seg == 2) ? Kp : 0) + kc * 32;
        uint32_t aB = sbase + buf * (2 * TILEB);
        uint32_t bB = aB + TILEB;
#pragma unroll
        for (int i = 0; i < 2; i++) {
            int u = tid + i * 256;
            int r = u >> 2, un = u & 3;
            uint32_t dst = aB + r * ROWB + un * 16;
            const __nv_bfloat16* src = A2 + (size_t)(bm + r) * KS + ka + un * 8;
            int sz = (bm + r < M) ? 16 : 0;
            CP_ASYNC16Z(dst, src, sz);
        }
#pragma unroll
        for (int i = 0; i < 2; i++) {
            int u = tid + i * 256;
            int r = u >> 2, un = u & 3;
            uint32_t dst = bB + r * ROWB + un * 16;
            const __nv_bfloat16* src = B2 + (size_t)(bn + r) * KS + kb + un * 8;
            CP_ASYNC16(dst, src);
        }
        CP_COMMIT();
    };

    float acc[2][8][4];
#pragma unroll
    for (int mt = 0; mt < 2; mt++)
#pragma unroll
        for (int nt = 0; nt < 8; nt++)
#pragma unroll
            for (int q = 0; q < 4; q++) acc[mt][nt][q] = 0.f;

    issue(0, 0);
    for (int c = 0; c < NK; c++) {
        if (c + 1 < NK) { issue(c + 1, (c + 1) & 1); CP_WAIT1(); }
        else            { CP_WAIT0(); }
        __syncthreads();

        uint32_t aB = sbase + (c & 1) * (2 * TILEB);
        uint32_t bB = aB + TILEB;

        uint32_t breg[8][4];
#pragma unroll
        for (int nt = 0; nt < 8; nt++) {
            uint32_t addr = bB + (uint32_t)((wn * 64 + nt * 8 + (lane & 7)) * ROWB
                                            + (lane >> 3) * 16);
            LDM_X4(breg[nt][0], breg[nt][1], breg[nt][2], breg[nt][3], addr);
        }
#pragma unroll
        for (int kt = 0; kt < 2; kt++) {
            uint32_t areg[2][4];
#pragma unroll
            for (int mt = 0; mt < 2; mt++) {
                uint32_t addr = aB + (uint32_t)((wm * 32 + mt * 16 + (lane & 15)) * ROWB
                                                + (kt * 2 + (lane >> 4)) * 16);
                LDM_X4(areg[mt][0], areg[mt][1], areg[mt][2], areg[mt][3], addr);
            }
#pragma unroll
            for (int mt = 0; mt < 2; mt++)
#pragma unroll
                for (int nt = 0; nt < 8; nt++)
                    MMA16816(acc[mt][nt], areg[mt],
                             breg[nt][kt * 2], breg[nt][kt * 2 + 1]);
        }
        __syncthreads();
    }

    // epilogue
    int gid = lane >> 2, tig = lane & 3;
#pragma unroll
    for (int mt = 0; mt < 2; mt++) {
        int row0 = bm + wm * 32 + mt * 16 + gid;
#pragma unroll
        for (int nt = 0; nt < 8; nt++) {
            int col = bn + wn * 64 + nt * 8 + 2 * tig;
            float2 v0 = make_float2(acc[mt][nt][0], acc[mt][nt][1]);
            float2 v1 = make_float2(acc[mt][nt][2], acc[mt][nt][3]);
            if (HAS_BIAS) {
                float bx = bias[col], by = bias[col + 1];
                v0.x += bx; v0.y += by; v1.x += bx; v1.y += by;
            }
            if (RELU_OUT) {
                v0.x = fmaxf(v0.x, 0.f); v0.y = fmaxf(v0.y, 0.f);
                v1.x = fmaxf(v1.x, 0.f); v1.y = fmaxf(v1.y, 0.f);
            }
            if (WRITE_SPLIT) {
                // out row stride 512: [hi(256) | lo(256)]
                if (row0 < M) {
                    __nv_bfloat16* rp = Cs + (size_t)row0 * 512;
                    Pack2 h, l;
                    split_bf16(v0.x, h.h[0], l.h[0]);
                    split_bf16(v0.y, h.h[1], l.h[1]);
                    *reinterpret_cast<uint32_t*>(rp + col)       = h.u;
                    *reinterpret_cast<uint32_t*>(rp + 256 + col) = l.u;
                }
                if (row0 + 8 < M) {
                    __nv_bfloat16* rp = Cs + (size_t)(row0 + 8) * 512;
                    Pack2 h, l;
                    split_bf16(v1.x, h.h[0], l.h[0]);
                    split_bf16(v1.y, h.h[1], l.h[1]);
                    *reinterpret_cast<uint32_t*>(rp + col)       = h.u;
                    *reinterpret_cast<uint32_t*>(rp + 256 + col) = l.u;
                }
            } else {
                if (row0 < M)
                    *reinterpret_cast<float2*>(C + (size_t)row0 * 256 + col) = v0;
                if (row0 + 8 < M)
                    *reinterpret_cast<float2*>(C + (size_t)(row0 + 8) * 256 + col) = v1;
            }
        }
    }
}

// ---------------- launch ----------------------------------------------------
extern "C" void kernel_launch(void* const* d_in, const int* in_sizes, int n_in,
                              void* d_out, int out_size) {
    const float* x  = (const float*)d_in[0];
    const int*   ei = (const int*)d_in[1];
    const float* W0 = (const float*)d_in[2],  *b0 = (const float*)d_in[3];
    const float* W1 = (const float*)d_in[4],  *b1 = (const float*)d_in[5];
    const float* W2 = (const float*)d_in[6],  *b2 = (const float*)d_in[7];
    const float* M1 = (const float*)d_in[8],  *m1b = (const float*)d_in[9];
    const float* M2 = (const float*)d_in[10], *m2b = (const float*)d_in[11];
    const float* M3 = (const float*)d_in[12], *m3b = (const float*)d_in[13];
    float* out = (float*)d_out;

    float *tmp;
    __nv_bfloat16 *bufA, *bufB, *w2;
    cudaGetSymbolAddress((void**)&tmp,  g_tmp);
    cudaGetSymbolAddress((void**)&bufA, g_bufA);
    cudaGetSymbolAddress((void**)&bufB, g_bufB);
    cudaGetSymbolAddress((void**)&w2,   g_w2);

    const int TPB = 256;
    int nb_nodes = (N_NODES + TPB - 1) / TPB;
    int nb_edges = (N_EDGES + TPB - 1) / TPB;

    cnt_zero_kernel<<<nb_nodes, TPB>>>();
    hist_kernel   <<<nb_edges, TPB>>>(ei);
    scan_kernel   <<<1, 1024>>>();
    scatter_kernel<<<nb_edges, TPB>>>(ei);

    // conversions
    wconv_kernel<<<(256 * 320 + 5 * 65536 + TPB - 1) / TPB, TPB>>>(W0, W1, W2, M1, M2, M3);
    a2x_kernel  <<<(N_NODES * 320 + TPB - 1) / TPB, TPB>>>(x, bufA);

    dim3 gg((N_NODES + 127) / 128, 2);
    int agg_blocks = (N_NODES * 32 + TPB - 1) / TPB;
    const size_t WSLOT = 163840;

    // conv0: A=bufA(Kp=320), W slot0 -> tmp; agg+relu -> bufB
    hgemm_kernel<false, false, false><<<gg, TPB>>>(bufA, w2, nullptr, tmp, nullptr, N_NODES, 320);
    agg_kernel<1><<<agg_blocks, TPB>>>(tmp, b0, bufB);
    // conv1
    hgemm_kernel<false, false, false><<<gg, TPB>>>(bufB, w2 + WSLOT, nullptr, tmp, nullptr, N_NODES, 256);
    agg_kernel<1><<<agg_blocks, TPB>>>(tmp, b1, bufA);
    // conv2 (no relu)
    hgemm_kernel<false, false, false><<<gg, TPB>>>(bufA, w2 + 2 * WSLOT, nullptr, tmp, nullptr, N_NODES, 256);
    agg_kernel<0><<<agg_blocks, TPB>>>(tmp, b2, bufB);
    // MLP1, MLP2: bias+relu, split output
    hgemm_kernel<true, true, true><<<gg, TPB>>>(bufB, w2 + 3 * WSLOT, m1b, nullptr, bufA, N_NODES, 256);
    hgemm_kernel<true, true, true><<<gg, TPB>>>(bufA, w2 + 4 * WSLOT, m2b, nullptr, bufB, N_NODES, 256);
    // MLP3: bias, fp32 out
    hgemm_kernel<true, false, false><<<gg, TPB>>>(bufB, w2 + 5 * WSLOT, m3b, out, nullptr, N_NODES, 256);
}